// round 11
// baseline (speedup 1.0000x reference)
#include <cuda_runtime.h>
#include <cuda_fp16.h>
#include <cstdint>

#define F 128
#define MAXN 100000
#define PITCH_H 136     // smem pitch in halves: 272B ≡ 4 banks mod 32 -> ldmatrix conflict-free
#define ELLW 64
#define GEMM_GRID 304   // 2 blocks per SM

// Static device scratch (cudaMalloc is forbidden)
__device__ uint16_t g_xh[(size_t)MAXN * F];     // x converted to fp16
__device__ uint16_t g_xw[(size_t)MAXN * F];     // fp16 XW scratch
__device__ uint16_t g_h[(size_t)MAXN * F];      // fp16 hidden scratch
__device__ int      g_deg[MAXN];
__device__ int      g_ell[(size_t)MAXN * ELLW];

// ---------------------------------------------------------------------------
__device__ __forceinline__ void mma_f16(float* c, const uint32_t* a, const uint32_t* b) {
    asm volatile(
        "mma.sync.aligned.m16n8k16.row.col.f32.f16.f16.f32 "
        "{%0,%1,%2,%3}, {%4,%5,%6,%7}, {%8,%9}, {%0,%1,%2,%3};"
        : "+f"(c[0]), "+f"(c[1]), "+f"(c[2]), "+f"(c[3])
        : "r"(a[0]), "r"(a[1]), "r"(a[2]), "r"(a[3]), "r"(b[0]), "r"(b[1]));
}

__device__ __forceinline__ void ldsm_x4(uint32_t& r0, uint32_t& r1, uint32_t& r2,
                                        uint32_t& r3, uint32_t addr) {
    asm volatile("ldmatrix.sync.aligned.m8n8.x4.shared.b16 {%0,%1,%2,%3}, [%4];"
                 : "=r"(r0), "=r"(r1), "=r"(r2), "=r"(r3) : "r"(addr));
}

__device__ __forceinline__ void stsm_x2(uint32_t addr, uint32_t r0, uint32_t r1) {
    asm volatile("stmatrix.sync.aligned.m8n8.x2.shared.b16 [%0], {%1,%2};"
                 :: "r"(addr), "r"(r0), "r"(r1));
}

__device__ __forceinline__ void cp16(uint32_t dst, const void* src, int sz) {
    asm volatile("cp.async.cg.shared.global [%0], [%1], 16, %2;"
                 :: "r"(dst), "l"(src), "r"(sz));
}
__device__ __forceinline__ void cp_commit() { asm volatile("cp.async.commit_group;"); }
template <int NN>
__device__ __forceinline__ void cp_wait() {
    asm volatile("cp.async.wait_group %0;" :: "n"(NN));
}

__device__ __forceinline__ float4 h4_to_f4(uint2 v) {
    __half2 a = *(__half2*)&v.x;
    __half2 b = *(__half2*)&v.y;
    float2 fa = __half22float2(a);
    float2 fb = __half22float2(b);
    return make_float4(fa.x, fa.y, fb.x, fb.y);
}

// ---------------------------------------------------------------------------
// x conversion: fp32 -> fp16 (feeds GEMM1; main stream)
// ---------------------------------------------------------------------------
__global__ void __launch_bounds__(256) k_conv(const float* __restrict__ x,
                                              uint16_t* __restrict__ xh, int total4) {
    int gid = blockIdx.x * 256 + threadIdx.x;
    if (gid < total4) {
        float4 v = ((const float4*)x)[gid];
        __half2 h01 = __floats2half2_rn(v.x, v.y);
        __half2 h23 = __floats2half2_rn(v.z, v.w);
        uint2 o;
        o.x = *(uint32_t*)&h01;
        o.y = *(uint32_t*)&h23;
        ((uint2*)xh)[gid] = o;
    }
}

// ---------------------------------------------------------------------------
// ELL build (side stream): inline int64/int32 detect, slot = atomicAdd(deg[c]),
// direct ELL write. deg pre-zeroed by memset on the same stream.
// ---------------------------------------------------------------------------
__global__ void __launch_bounds__(256) k_ell(const int* __restrict__ ei, int E) {
    __shared__ int s_is64;
    int t = threadIdx.x;
    if (t < 32) {
        int n = (E < 16) ? E : 16;
        int bad = (t < n) ? (ei[2 * t + 1] != 0) : 0;
        bad = __any_sync(0xffffffffu, bad);
        if (t == 0) s_is64 = !bad;
    }
    __syncthreads();
    int is64 = s_is64;
    int e = blockIdx.x * 256 + t;
    if (e < E) {
        int r, c;
        if (is64) {
            r = ei[2 * e];
            c = ei[2 * E + 2 * e];
        } else {
            r = ei[e];
            c = ei[E + e];
        }
        int p = atomicAdd(&g_deg[c], 1);
        if (p < ELLW) g_ell[(size_t)c * ELLW + p] = r;
    }
}

// ---------------------------------------------------------------------------
// Persistent double-buffered fp16 tensor-core GEMM:
// C[N,128] (fp16) = A[N,128] (fp16) * W[128,128] (fp32 -> fp16).
// mma.m16n8k16 + ldmatrix fragments; stmatrix epilogue staged through the
// consumed A buffer -> coalesced STG.128. 304 blocks (2/SM) x 256 threads.
// ---------------------------------------------------------------------------
__global__ void __launch_bounds__(256, 2) k_gemm_tc(const __half* __restrict__ A,
                                                    const float* __restrict__ W,
                                                    uint16_t* __restrict__ C,
                                                    int N, int ntiles) {
    extern __shared__ char smraw[];
    __half* Wt = (__half*)smraw;                       // 128 * PITCH_H halves
    __half* As0 = (__half*)(smraw + 128 * PITCH_H * 2);
    __half* As1 = As0 + 128 * PITCH_H;
    uint32_t WtA = (uint32_t)__cvta_generic_to_shared(Wt);
    uint32_t AsA[2] = {(uint32_t)__cvta_generic_to_shared(As0),
                       (uint32_t)__cvta_generic_to_shared(As1)};
    int t = threadIdx.x;

    // Stage W: fp32 [k][n] -> fp16 Wt[n][k]
#pragma unroll
    for (int i = 0; i < 16; i++) {
        int lin = t + i * 256;             // 4096 float4 = 16384 floats
        int k = lin >> 5;
        int n4 = (lin & 31) * 4;
        float4 v = *(const float4*)&W[k * 128 + n4];
        Wt[(n4 + 0) * PITCH_H + k] = __float2half_rn(v.x);
        Wt[(n4 + 1) * PITCH_H + k] = __float2half_rn(v.y);
        Wt[(n4 + 2) * PITCH_H + k] = __float2half_rn(v.z);
        Wt[(n4 + 3) * PITCH_H + k] = __float2half_rn(v.w);
    }

    int wid = t >> 5;
    int lane = t & 31;
    int l16 = lane & 15;
    int wm = (wid & 3) * 32;   // warp m offset
    int wn = (wid >> 2) * 64;  // warp n offset

    // ldmatrix per-lane base offsets (halves)
    int arow = lane & 15;
    int akoff = (lane & 16) ? 8 : 0;
    int a_off[2];
#pragma unroll
    for (int mt = 0; mt < 2; mt++)
        a_off[mt] = (wm + mt * 16 + arow) * PITCH_H + akoff;
    int brow = (lane & 7) + ((lane & 16) ? 8 : 0);
    int bkoff = (lane & 8) ? 8 : 0;
    int b_off[4];
#pragma unroll
    for (int p = 0; p < 4; p++)
        b_off[p] = (wn + p * 16 + brow) * PITCH_H + bkoff;

    auto stage = [&](uint32_t dst, int tile) {
        int rowBase = tile * 128;
#pragma unroll
        for (int i = 0; i < 8; i++) {
            int lin = t + i * 256;         // 2048 x 16B chunks
            int r = lin >> 4;
            int c8 = lin & 15;
            int grow = rowBase + r;
            int cl = (grow < N) ? grow : (N - 1);
            cp16(dst + (uint32_t)(r * PITCH_H + c8 * 8) * 2,
                 (const char*)A + ((size_t)cl * F + c8 * 8) * 2,
                 (grow < N) ? 16 : 0);
        }
    };

    int tile0 = blockIdx.x;
    if (tile0 < ntiles) stage(AsA[0], tile0);
    cp_commit();

    int b = 0;
    for (int tile = tile0; tile < ntiles; tile += GEMM_GRID) {
        int next = tile + GEMM_GRID;
        if (next < ntiles) {
            stage(AsA[b ^ 1], next);
            cp_commit();
            cp_wait<1>();
        } else {
            cp_commit();
            cp_wait<0>();
        }
        __syncthreads();

        float acc[2][8][4];
#pragma unroll
        for (int mt = 0; mt < 2; mt++)
#pragma unroll
            for (int nt = 0; nt < 8; nt++)
#pragma unroll
                for (int j = 0; j < 4; j++) acc[mt][nt][j] = 0.0f;

        uint32_t Ab = AsA[b];
#pragma unroll
        for (int ks = 0; ks < 8; ks++) {
            int k0 = ks * 16;
            uint32_t af[2][4];
#pragma unroll
            for (int mt = 0; mt < 2; mt++)
                ldsm_x4(af[mt][0], af[mt][1], af[mt][2], af[mt][3],
                        Ab + (uint32_t)(a_off[mt] + k0) * 2);
            uint32_t bf[8][2];
#pragma unroll
            for (int p = 0; p < 4; p++)
                ldsm_x4(bf[2 * p][0], bf[2 * p][1], bf[2 * p + 1][0],
                        bf[2 * p + 1][1], WtA + (uint32_t)(b_off[p] + k0) * 2);
#pragma unroll
            for (int mt = 0; mt < 2; mt++)
#pragma unroll
                for (int nt = 0; nt < 8; nt++) mma_f16(acc[mt][nt], af[mt], bf[nt]);
        }
        __syncthreads();  // everyone done reading As[b]; reuse as epilogue staging

        // stmatrix: acc -> fp16 tile in As[b] (lanes 0-15 supply row addrs)
#pragma unroll
        for (int mt = 0; mt < 2; mt++) {
#pragma unroll
            for (int nt = 0; nt < 8; nt++) {
                uint32_t addr = Ab +
                    (uint32_t)((wm + mt * 16 + l16) * PITCH_H + wn + nt * 8) * 2;
                __half2 lo = __floats2half2_rn(acc[mt][nt][0], acc[mt][nt][1]);
                __half2 hi = __floats2half2_rn(acc[mt][nt][2], acc[mt][nt][3]);
                stsm_x2(addr, *(uint32_t*)&lo, *(uint32_t*)&hi);
            }
        }
        __syncthreads();

        // Coalesced write-out: 2048 uint4, 8 per thread
        int rowBase = tile * 128;
        const __half* Sb = (b == 0) ? As0 : As1;
#pragma unroll
        for (int i = 0; i < 8; i++) {
            int lin = t + i * 256;
            int r = lin >> 4;
            int c16 = lin & 15;
            int grow = rowBase + r;
            if (grow < N) {
                uint4 v = *(const uint4*)&Sb[r * PITCH_H + c16 * 8];
                *(uint4*)&C[(size_t)grow * F + c16 * 8] = v;
            }
        }
        __syncthreads();  // staging free before next prefetch targets it
        b ^= 1;
    }
}

// ---------------------------------------------------------------------------
// Aggregation: one warp per node over ELL. dinv computed inline from deg
// (rsqrtf(deg+1)); indices+dinv broadcast via shfl; gathers batched 2-wide.
// ---------------------------------------------------------------------------
template <int RELU, int OUTHALF>
__global__ void __launch_bounds__(256) k_agg(const uint16_t* __restrict__ XW,
                                             const float* __restrict__ bias,
                                             void* __restrict__ outp, int N) {
    int node = (blockIdx.x * blockDim.x + threadIdx.x) >> 5;
    int lane = threadIdx.x & 31;
    if (node >= N) return;

    int d = g_deg[node];
    float dc = rsqrtf((float)d + 1.0f);
    int cnt = (d < ELLW) ? d : ELLW;

    const int* nb = g_ell + (size_t)node * ELLW;
    int idx0 = (lane < cnt) ? nb[lane] : 0;
    int idx1 = (lane + 32 < cnt) ? nb[lane + 32] : 0;
    float dv0 = (lane < cnt) ? rsqrtf((float)g_deg[idx0] + 1.0f) : 0.0f;
    float dv1 = (lane + 32 < cnt) ? rsqrtf((float)g_deg[idx1] + 1.0f) : 0.0f;

    uint2 sv = ((const uint2*)(XW + (size_t)node * F))[lane];
    float4 s = h4_to_f4(sv);
    float w = dc * dc;
    float4 acc = make_float4(s.x * w, s.y * w, s.z * w, s.w * w);

    int j = 0;
    for (; j + 2 <= cnt; j += 2) {
        int sa = __shfl_sync(0xffffffffu, (j < 32) ? idx0 : idx1, j & 31);
        float da = __shfl_sync(0xffffffffu, (j < 32) ? dv0 : dv1, j & 31);
        int jb = j + 1;
        int sb = __shfl_sync(0xffffffffu, (jb < 32) ? idx0 : idx1, jb & 31);
        float db = __shfl_sync(0xffffffffu, (jb < 32) ? dv0 : dv1, jb & 31);
        uint2 ua = ((const uint2*)(XW + (size_t)sa * F))[lane];
        uint2 ub = ((const uint2*)(XW + (size_t)sb * F))[lane];
        float na = da * dc;
        float nbm = db * dc;
        float4 fa = h4_to_f4(ua);
        float4 fb = h4_to_f4(ub);
        acc.x += fa.x * na + fb.x * nbm;
        acc.y += fa.y * na + fb.y * nbm;
        acc.z += fa.z * na + fb.z * nbm;
        acc.w += fa.w * na + fb.w * nbm;
    }
    if (j < cnt) {
        int sa = __shfl_sync(0xffffffffu, (j < 32) ? idx0 : idx1, j & 31);
        float da = __shfl_sync(0xffffffffu, (j < 32) ? dv0 : dv1, j & 31);
        uint2 ua = ((const uint2*)(XW + (size_t)sa * F))[lane];
        float na = da * dc;
        float4 fa = h4_to_f4(ua);
        acc.x += fa.x * na;
        acc.y += fa.y * na;
        acc.z += fa.z * na;
        acc.w += fa.w * na;
    }

    float4 bb = ((const float4*)bias)[lane];
    acc.x += bb.x; acc.y += bb.y; acc.z += bb.z; acc.w += bb.w;
    if (RELU) {
        acc.x = fmaxf(acc.x, 0.0f);
        acc.y = fmaxf(acc.y, 0.0f);
        acc.z = fmaxf(acc.z, 0.0f);
        acc.w = fmaxf(acc.w, 0.0f);
    }
    if (OUTHALF) {
        __half2 h01 = __floats2half2_rn(acc.x, acc.y);
        __half2 h23 = __floats2half2_rn(acc.z, acc.w);
        uint2 o;
        o.x = *(uint32_t*)&h01;
        o.y = *(uint32_t*)&h23;
        ((uint2*)((uint16_t*)outp + (size_t)node * F))[lane] = o;
    } else {
        ((float4*)((float*)outp + (size_t)node * F))[lane] = acc;
    }
}

// ---------------------------------------------------------------------------
extern "C" void kernel_launch(void* const* d_in, const int* in_sizes, int n_in,
                              void* d_out, int out_size) {
    const float* x = (const float*)d_in[0];
    const int* ei = (const int*)d_in[1];
    const float* W1 = (const float*)d_in[2];
    const float* b1 = (const float*)d_in[3];
    const float* W2 = (const float*)d_in[4];
    const float* b2 = (const float*)d_in[5];
    float* out = (float*)d_out;

    int N = in_sizes[0] / F;
    int E = in_sizes[1] / 2;

    uint16_t *xhp, *xwp, *hp;
    int* degp;
    cudaGetSymbolAddress((void**)&xhp, g_xh);
    cudaGetSymbolAddress((void**)&xwp, g_xw);
    cudaGetSymbolAddress((void**)&hp, g_h);
    cudaGetSymbolAddress((void**)&degp, g_deg);

    const int smem_bytes = 3 * 128 * PITCH_H * 2;  // Wt + 2 A buffers = 104448
    // One-time resource setup (host-side; no device allocation)
    static cudaStream_t s2 = nullptr;
    static cudaEvent_t ev_fork = nullptr, ev_join = nullptr;
    if (s2 == nullptr) {
        cudaFuncSetAttribute(k_gemm_tc, cudaFuncAttributeMaxDynamicSharedMemorySize,
                             smem_bytes);
        cudaStreamCreateWithFlags(&s2, cudaStreamNonBlocking);
        cudaEventCreateWithFlags(&ev_fork, cudaEventDisableTiming);
        cudaEventCreateWithFlags(&ev_join, cudaEventDisableTiming);
    }

    int ntiles = (N + 127) / 128;
    int agg_grid = (N + 7) / 8;

    // Fork: side stream builds ELL (memset + edge kernel) while the main
    // stream converts x and runs GEMM1. Join before agg1 (first ELL consumer).
    cudaEventRecord(ev_fork, 0);
    cudaStreamWaitEvent(s2, ev_fork, 0);
    cudaMemsetAsync(degp, 0, (size_t)N * sizeof(int), s2);
    k_ell<<<(E + 255) / 256, 256, 0, s2>>>(ei, E);
    cudaEventRecord(ev_join, s2);

    k_conv<<<(N * (F / 4) + 255) / 256, 256>>>(x, xhp, N * (F / 4));
    k_gemm_tc<<<GEMM_GRID, 256, smem_bytes>>>((const __half*)xhp, W1, xwp, N,
                                              ntiles);
    cudaStreamWaitEvent(0, ev_join, 0);

    k_agg<1, 1><<<agg_grid, 256>>>(xwp, b1, hp, N);
    k_gemm_tc<<<GEMM_GRID, 256, smem_bytes>>>((const __half*)hp, W2, xwp, N,
                                              ntiles);
    k_agg<0, 0><<<agg_grid, 256>>>(xwp, b2, out, N);
}